// round 1
// baseline (speedup 1.0000x reference)
#include <cuda_runtime.h>
#include <cstdint>

#define NV 50000
#define NE 400000
#define CN 12500
#define NROWS 100000   /* NV * 2 (node, batch) rows */

typedef unsigned long long ull;

// ---------------- scratch (static device memory; no allocation) ----------------
__device__ int   d_degcnt[NV];
__device__ float d_degF[NV];
__device__ int   d_rowptr[NV + 1];
__device__ int   d_cursor[NV];
__device__ float d_deginv[NV];
__device__ int   d_blocksums[128];
__device__ int   d_sorted_end[NE];
__device__ float d_sorted_val[NE];
__device__ float d_z0[(size_t)NV * 128];    // [v][b*64+k]
__device__ float d_out0[(size_t)NV * 256];  // [v][b*128+o]
__device__ float d_z1[(size_t)NV * 256];
__device__ float d_out1[(size_t)NV * 256];

// ---------------- f32x2 packed helpers (Blackwell FFMA2) ----------------
__device__ __forceinline__ ull pk2(float x, float y) {
    ull r; asm("mov.b64 %0, {%1, %2};" : "=l"(r) : "f"(x), "f"(y)); return r;
}
__device__ __forceinline__ void upk2(ull a, float& x, float& y) {
    asm("mov.b64 {%0, %1}, %2;" : "=f"(x), "=f"(y) : "l"(a));
}
__device__ __forceinline__ ull f2fma(ull a, ull b, ull c) {
    ull d; asm("fma.rn.f32x2 %0, %1, %2, %3;" : "=l"(d) : "l"(a), "l"(b), "l"(c)); return d;
}

// ---------------- graph preprocessing ----------------
__global__ void k_zero() {
    int i = blockIdx.x * blockDim.x + threadIdx.x;
    if (i < NV) { d_degcnt[i] = 0; d_degF[i] = 0.f; d_cursor[i] = 0; }
}

__global__ void k_hist(const int* __restrict__ Es, const float* __restrict__ one) {
    int e = blockIdx.x * blockDim.x + threadIdx.x;
    if (e < NE) {
        int s = Es[e];
        atomicAdd(&d_degcnt[s], 1);
        atomicAdd(&d_degF[s], one[e]);
    }
}

__global__ void k_scanA() {
    __shared__ int s[512];
    int gid = blockIdx.x * 512 + threadIdx.x;
    int val = (gid < NV) ? d_degcnt[gid] : 0;
    s[threadIdx.x] = val;
    __syncthreads();
    for (int off = 1; off < 512; off <<= 1) {
        int t = (threadIdx.x >= off) ? s[threadIdx.x - off] : 0;
        __syncthreads();
        s[threadIdx.x] += t;
        __syncthreads();
    }
    if (gid < NV) d_rowptr[gid + 1] = s[threadIdx.x];
    if (threadIdx.x == 511) d_blocksums[blockIdx.x] = s[511];
}

__global__ void k_scanB(int nb) {
    __shared__ int s[128];
    int t = threadIdx.x;
    int v = (t < nb) ? d_blocksums[t] : 0;
    s[t] = v;
    __syncthreads();
    for (int off = 1; off < 128; off <<= 1) {
        int u = (t >= off) ? s[t - off] : 0;
        __syncthreads();
        s[t] += u;
        __syncthreads();
    }
    if (t < nb) d_blocksums[t] = s[t] - v;   // exclusive
}

__global__ void k_scanC() {
    int gid = blockIdx.x * 512 + threadIdx.x;
    if (gid < NV) {
        d_rowptr[gid + 1] += d_blocksums[blockIdx.x];
        d_deginv[gid] = 1.0f / fmaxf(d_degF[gid], 1.0f);
    }
    if (gid == 0) d_rowptr[0] = 0;
}

__global__ void k_fill(const int* __restrict__ Es, const int* __restrict__ Ee,
                       const float* __restrict__ adj) {
    int e = blockIdx.x * blockDim.x + threadIdx.x;
    if (e < NE) {
        int s = Es[e];
        int p = atomicAdd(&d_cursor[s], 1);
        int o = d_rowptr[s] + p;
        d_sorted_end[o] = Ee[e];
        d_sorted_val[o] = adj[e];
    }
}

// ---------------- aggregation (gather, no atomics) ----------------
// z0[v][b*64+k] = deg_inv[v] * sum_e adj_e * x[b][end_e][k]
__global__ void k_gather64(const float* __restrict__ x) {
    int v = blockIdx.x * 2 + (threadIdx.x >> 7);
    int t = threadIdx.x & 127;
    int b = t >> 6, k = t & 63;
    const float* xb = x + ((size_t)b * NV) * 64 + k;
    int i = d_rowptr[v], end = d_rowptr[v + 1];
    float acc = 0.f;
    for (; i < end; i++) {
        int u = d_sorted_end[i];
        float w = d_sorted_val[i];
        acc = fmaf(w, xb[(size_t)u * 64], acc);
    }
    d_z0[(size_t)v * 128 + t] = acc * d_deginv[v];
}

// z1[v][t] = deg_inv[v] * sum_e adj_e * out0[end_e][t],  t in [0,256)
__global__ void k_gather128() {
    int v = blockIdx.x;
    int t = threadIdx.x;
    int i = d_rowptr[v], end = d_rowptr[v + 1];
    float acc = 0.f;
    for (; i < end; i++) {
        int u = d_sorted_end[i];
        float w = d_sorted_val[i];
        acc = fmaf(w, d_out0[(size_t)u * 256 + t], acc);
    }
    d_z1[(size_t)v * 256 + t] = acc * d_deginv[v];
}

// ---------------- fused concat-GEMM: out = act([A_self | A_agg] @ [W_self; W_nb] + b) ----------------
// Block 256 threads, tile 64 rows x 128 cols. A tile stored k-major in shared
// (stride 68 for 16B alignment + low bank conflicts). Each thread: 8 row-pairs
// (packed in f32x2 lanes) x 2 cols -> 16 FFMA2 per k.
template <int K, bool L0>
__global__ void __launch_bounds__(256) k_gemm(const float* __restrict__ xin,
                                              const float* __restrict__ Wself,
                                              const float* __restrict__ Wnb,
                                              const float* __restrict__ bias,
                                              int ntiles) {
    constexpr int KH = K / 2;
    constexpr int AST = 68;
    extern __shared__ float sm[];
    float* Ws = sm;             // K * 128
    float* As = sm + K * 128;   // K * AST (k-major)

    // load concatenated weights once
    for (int i4 = threadIdx.x; i4 < K * 32; i4 += 256) {
        int idx = i4 * 4;
        int k = idx >> 7, o = idx & 127;
        const float* src = (k < KH) ? (Wself + k * 128 + o) : (Wnb + (k - KH) * 128 + o);
        *(float4*)(Ws + idx) = *(const float4*)src;
    }

    int p   = threadIdx.x & 63;   // col pair -> cols {2p, 2p+1}
    int rgq = threadIdx.x >> 6;   // 0..3 -> rows rgq*16 .. rgq*16+15
    float2 bia = *(const float2*)(bias + 2 * p);

    // A-load mapping: 4 threads per row, 64B-contiguous chunks per j
    int rr = threadIdx.x >> 2;            // 0..63
    int klane = (threadIdx.x & 3) * 4;    // 0,4,8,12
    float* outp = L0 ? d_out0 : d_out1;
    __syncthreads();

    for (int tile = blockIdx.x; tile < ntiles; tile += gridDim.x) {
        int row0 = tile * 64;
        {
            int row = row0 + rr;
            bool ok = row < NROWS;
            const float* sA;
            const float* sB;
            if (L0) {
                sA = xin + ((size_t)(row & 1) * NV + (row >> 1)) * 64;  // x row
                sB = d_z0 + (size_t)row * 64;
            } else {
                sA = d_out0 + (size_t)row * 128;
                sB = d_z1 + (size_t)row * 128;
            }
#pragma unroll
            for (int j = 0; j < K / 16; j++) {
                int k = klane + 16 * j;
                float4 v4 = make_float4(0.f, 0.f, 0.f, 0.f);
                if (ok) v4 = (k < KH) ? *(const float4*)(sA + k) : *(const float4*)(sB + (k - KH));
                As[(k + 0) * AST + rr] = v4.x;
                As[(k + 1) * AST + rr] = v4.y;
                As[(k + 2) * AST + rr] = v4.z;
                As[(k + 3) * AST + rr] = v4.w;
            }
        }
        __syncthreads();

        ull acc0[8], acc1[8];
#pragma unroll
        for (int i = 0; i < 8; i++) { acc0[i] = 0ull; acc1[i] = 0ull; }
        const float* asb = As + rgq * 16;
#pragma unroll 2
        for (int k = 0; k < K; k++) {
            float2 wv = *(const float2*)(Ws + k * 128 + 2 * p);
            ull w0 = pk2(wv.x, wv.x), w1 = pk2(wv.y, wv.y);
            const float* ak = asb + (size_t)k * AST;
#pragma unroll
            for (int h = 0; h < 4; h++) {
                ulonglong2 a = *(const ulonglong2*)(ak + 4 * h);
                acc0[2 * h]     = f2fma(a.x, w0, acc0[2 * h]);
                acc1[2 * h]     = f2fma(a.x, w1, acc1[2 * h]);
                acc0[2 * h + 1] = f2fma(a.y, w0, acc0[2 * h + 1]);
                acc1[2 * h + 1] = f2fma(a.y, w1, acc1[2 * h + 1]);
            }
        }

#pragma unroll
        for (int i = 0; i < 8; i++) {
            float x0, x1, y0, y1;
            upk2(acc0[i], x0, x1);
            upk2(acc1[i], y0, y1);
            float o00 = x0 + bia.x, o01 = y0 + bia.y;
            float o10 = x1 + bia.x, o11 = y1 + bia.y;
            if (L0) {
                o00 = (o00 >= 0.f) ? o00 : 0.2f * o00;
                o01 = (o01 >= 0.f) ? o01 : 0.2f * o01;
                o10 = (o10 >= 0.f) ? o10 : 0.2f * o10;
                o11 = (o11 >= 0.f) ? o11 : 0.2f * o11;
            }
            int r0 = row0 + rgq * 16 + 2 * i;
            if (r0 < NROWS)     *(float2*)(outp + (size_t)r0 * 128 + 2 * p)       = make_float2(o00, o01);
            if (r0 + 1 < NROWS) *(float2*)(outp + (size_t)(r0 + 1) * 128 + 2 * p) = make_float2(o10, o11);
        }
        __syncthreads();
    }
}

// ---------------- final: pool(out1) + (pool(x) @ W_res + sw * b_res) ----------------
__global__ void __launch_bounds__(256) k_final(const float* __restrict__ x,
                                               const int* __restrict__ asgnIdx,
                                               const float* __restrict__ asgnVal,
                                               const float* __restrict__ Wres,
                                               const float* __restrict__ bres,
                                               float* __restrict__ out) {
    __shared__ float xps[4][64];
    int sub = threadIdx.x >> 6;     // row slot 0..3
    int p = threadIdx.x & 63;       // col pair
    int r = blockIdx.x * 4 + sub;   // r = c*2 + b
    bool ok = r < 2 * CN;
    int c = r >> 1, b = r & 1;
    const int* fine = asgnIdx + NV;   // second row of [2, NV]
    float sw = 0.f;
    float2 p1 = make_float2(0.f, 0.f);
    if (ok) {
        int i0 = 4 * c;
        float a = 0.f;
#pragma unroll
        for (int j = 0; j < 4; j++) {
            int f = fine[i0 + j];
            float w = asgnVal[i0 + j];
            a = fmaf(w, x[((size_t)b * NV + f) * 64 + p], a);
            sw += w;
            float2 o1 = *(const float2*)(&d_out1[(size_t)f * 256 + b * 128 + 2 * p]);
            p1.x = fmaf(w, o1.x, p1.x);
            p1.y = fmaf(w, o1.y, p1.y);
        }
        xps[sub][p] = a;
    }
    __syncthreads();
    if (ok) {
        float2 br = *(const float2*)(bres + 2 * p);
        float accx = p1.x + sw * br.x;
        float accy = p1.y + sw * br.y;
#pragma unroll 8
        for (int k = 0; k < 64; k++) {
            float xk = xps[sub][k];
            float2 w2 = *(const float2*)(Wres + k * 128 + 2 * p);
            accx = fmaf(xk, w2.x, accx);
            accy = fmaf(xk, w2.y, accy);
        }
        *(float2*)(out + ((size_t)b * CN + c) * 128 + 2 * p) = make_float2(accx, accy);
    }
}

// ---------------- launch ----------------
extern "C" void kernel_launch(void* const* d_in, const int* in_sizes, int n_in,
                              void* d_out, int out_size) {
    const float* x       = (const float*)d_in[0];
    const float* adjVal  = (const float*)d_in[1];
    const float* edgeOne = (const float*)d_in[2];
    const int*   E_start = (const int*)d_in[3];
    const int*   E_end   = (const int*)d_in[4];
    const int*   asgnIdx = (const int*)d_in[5];
    const float* asgnVal = (const float*)d_in[6];
    const float* W_res   = (const float*)d_in[7];
    const float* b_res   = (const float*)d_in[8];
    const float* W0s     = (const float*)d_in[9];
    const float* W0n     = (const float*)d_in[10];
    const float* b0      = (const float*)d_in[11];
    const float* W1s     = (const float*)d_in[12];
    const float* W1n     = (const float*)d_in[13];
    const float* b1      = (const float*)d_in[14];
    float* out = (float*)d_out;

    const int NB = (NV + 511) / 512;            // 98
    const int NTILES = (NROWS + 63) / 64;       // 1563
    size_t smA = (size_t)(128 * 128 + 128 * 68) * 4;  // 100352 B
    size_t smB = (size_t)(256 * 128 + 256 * 68) * 4;  // 200704 B
    cudaFuncSetAttribute(k_gemm<128, true>,  cudaFuncAttributeMaxDynamicSharedMemorySize, (int)smA);
    cudaFuncSetAttribute(k_gemm<256, false>, cudaFuncAttributeMaxDynamicSharedMemorySize, (int)smB);

    k_zero<<<(NV + 255) / 256, 256>>>();
    k_hist<<<(NE + 255) / 256, 256>>>(E_start, edgeOne);
    k_scanA<<<NB, 512>>>();
    k_scanB<<<1, 128>>>(NB);
    k_scanC<<<NB, 512>>>();
    k_fill<<<(NE + 255) / 256, 256>>>(E_start, E_end, adjVal);

    k_gather64<<<NV / 2, 256>>>(x);
    k_gemm<128, true><<<296, 256, smA>>>(x, W0s, W0n, b0, NTILES);
    k_gather128<<<NV, 256>>>();
    k_gemm<256, false><<<148, 256, smB>>>(x, W1s, W1n, b1, NTILES);
    k_final<<<(2 * CN + 3) / 4, 256>>>(x, asgnIdx, asgnVal, W_res, b_res, out);
}

// round 4
// speedup vs baseline: 1.2456x; 1.2456x over previous
#include <cuda_runtime.h>
#include <cuda_bf16.h>
#include <cstdint>

#define NV 50000
#define NE 400000
#define CN 12500
#define NROWS 100000
#define NTILES 782      /* ceil(100000/128) */
#define BST 72          /* bf16 elems per smem row (64 data + 8 pad) */

typedef unsigned long long ull;

// ---------------- scratch (static device memory) ----------------
__device__ int   d_degcnt[NV];
__device__ float d_degF[NV];
__device__ int   d_rowptr[NV + 1];
__device__ int   d_cursor[NV];
__device__ float d_deginv[NV];
__device__ int   d_blocksums[128];
__device__ int   d_sorted_end[NE];
__device__ float d_sorted_val[NE];
__device__ float d_z0[(size_t)NV * 128];    // [v][b*64+k]
__device__ float d_out0[(size_t)NV * 256];  // [v][b*128+o]
__device__ float d_z1[(size_t)NV * 256];
__device__ float d_out1[(size_t)NV * 256];
// Pre-converted bf16 weight images, padded layout: ((chunk*2+half)*128 + n)*BST + k
__device__ uint4 d_Bimg0[(2 * 2 * 128 * BST * 2) / 16];   // L0: 2 chunks x {hi,lo}
__device__ uint4 d_Bimg1[(4 * 2 * 128 * BST * 2) / 16];   // L1: 4 chunks x {hi,lo}

// ---------------- helpers ----------------
__device__ __forceinline__ uint32_t smem_u32(const void* p) {
    uint32_t a;
    asm("{ .reg .u64 t; cvta.to.shared.u64 t, %1; cvt.u32.u64 %0, t; }" : "=r"(a) : "l"(p));
    return a;
}
__device__ __forceinline__ void ldmat4(uint32_t* r, uint32_t addr) {
    asm volatile("ldmatrix.sync.aligned.m8n8.x4.shared.b16 {%0,%1,%2,%3}, [%4];"
                 : "=r"(r[0]), "=r"(r[1]), "=r"(r[2]), "=r"(r[3]) : "r"(addr));
}
__device__ __forceinline__ void mma_bf16(float* d, const uint32_t* a, const uint32_t* b) {
    asm volatile("mma.sync.aligned.m16n8k16.row.col.f32.bf16.bf16.f32 "
                 "{%0,%1,%2,%3}, {%4,%5,%6,%7}, {%8,%9}, {%0,%1,%2,%3};"
                 : "+f"(d[0]), "+f"(d[1]), "+f"(d[2]), "+f"(d[3])
                 : "r"(a[0]), "r"(a[1]), "r"(a[2]), "r"(a[3]), "r"(b[0]), "r"(b[1]));
}
__device__ __forceinline__ float bfhi(float x) {
    return __bfloat162float(__float2bfloat16(x));
}
__device__ __forceinline__ unsigned short bfb(float x) {
    return __bfloat16_as_ushort(__float2bfloat16(x));
}

// ---------------- k_prep: zero scratch + build padded bf16 hi/lo weight images ----------------
__global__ void k_prep(const float* __restrict__ W0s, const float* __restrict__ W0n,
                       const float* __restrict__ W1s, const float* __restrict__ W1n) {
    int gt = blockIdx.x * blockDim.x + threadIdx.x;
    int stride = gridDim.x * blockDim.x;
    for (int i = gt; i < NV; i += stride) {
        d_degcnt[i] = 0; d_degF[i] = 0.f; d_cursor[i] = 0;
    }
    // items: L0 = 2 chunks * 128 n * 64 k = 16384; L1 = 32768
    for (int it = gt; it < 49152; it += stride) {
        bool isL1 = it >= 16384;
        int loc = isL1 ? (it - 16384) : it;
        int c = loc >> 13;          // 8192 items per chunk
        int rem = loc & 8191;
        int n = rem >> 6;
        int kk = rem & 63;
        int k = c * 64 + kk;
        int KH = isL1 ? 128 : 64;
        const float* W;
        if (isL1) W = (k < KH) ? W1s : (W1n - (size_t)KH * 128);
        else      W = (k < KH) ? W0s : (W0n - (size_t)KH * 128);
        float v = W[(size_t)k * 128 + n];
        float hi = bfhi(v);
        __nv_bfloat16* img = isL1 ? (__nv_bfloat16*)d_Bimg1 : (__nv_bfloat16*)d_Bimg0;
        ((unsigned short*)img)[((size_t)(c * 2 + 0) * 128 + n) * BST + kk] = bfb(v);
        ((unsigned short*)img)[((size_t)(c * 2 + 1) * 128 + n) * BST + kk] = bfb(v - hi);
    }
}

// ---------------- graph preprocessing ----------------
__global__ void k_hist(const int* __restrict__ Es, const float* __restrict__ one) {
    int e = blockIdx.x * blockDim.x + threadIdx.x;
    if (e < NE) {
        int s = Es[e];
        atomicAdd(&d_degcnt[s], 1);
        atomicAdd(&d_degF[s], one[e]);
    }
}

__global__ void k_scanA() {
    __shared__ int s[512];
    int gid = blockIdx.x * 512 + threadIdx.x;
    int val = (gid < NV) ? d_degcnt[gid] : 0;
    s[threadIdx.x] = val;
    __syncthreads();
    for (int off = 1; off < 512; off <<= 1) {
        int t = (threadIdx.x >= off) ? s[threadIdx.x - off] : 0;
        __syncthreads();
        s[threadIdx.x] += t;
        __syncthreads();
    }
    if (gid < NV) d_rowptr[gid + 1] = s[threadIdx.x];
    if (threadIdx.x == 511) d_blocksums[blockIdx.x] = s[511];
}

// merged scanB + scanC: each block redundantly scans the 98 block sums
__global__ void k_scanC2(int nb) {
    __shared__ int s[512];
    int t = threadIdx.x;
    s[t] = (t < nb) ? d_blocksums[t] : 0;
    __syncthreads();
    for (int off = 1; off < 512; off <<= 1) {
        int u = (t >= off) ? s[t - off] : 0;
        __syncthreads();
        s[t] += u;
        __syncthreads();
    }
    int boff = (blockIdx.x > 0) ? s[blockIdx.x - 1] : 0;
    int gid = blockIdx.x * 512 + t;
    if (gid < NV) {
        d_rowptr[gid + 1] += boff;
        d_deginv[gid] = 1.0f / fmaxf(d_degF[gid], 1.0f);
    }
    if (gid == 0) d_rowptr[0] = 0;
}

__global__ void k_fill(const int* __restrict__ Es, const int* __restrict__ Ee,
                       const float* __restrict__ adj) {
    int e = blockIdx.x * blockDim.x + threadIdx.x;
    if (e < NE) {
        int s = Es[e];
        int p = atomicAdd(&d_cursor[s], 1);
        int o = d_rowptr[s] + p;
        d_sorted_end[o] = Ee[e];
        d_sorted_val[o] = adj[e];
    }
}

// ---------------- aggregation (gather, no atomics) ----------------
__global__ void k_gather64(const float* __restrict__ x) {
    int v = blockIdx.x * 2 + (threadIdx.x >> 7);
    int t = threadIdx.x & 127;
    int b = t >> 6, k = t & 63;
    const float* xb = x + ((size_t)b * NV) * 64 + k;
    int i = d_rowptr[v], end = d_rowptr[v + 1];
    float acc = 0.f;
    for (; i < end; i++) {
        int u = d_sorted_end[i];
        float w = d_sorted_val[i];
        acc = fmaf(w, xb[(size_t)u * 64], acc);
    }
    d_z0[(size_t)v * 128 + t] = acc * d_deginv[v];
}

__global__ void k_gather128() {
    int v = blockIdx.x;
    int t = threadIdx.x;
    int i = d_rowptr[v], end = d_rowptr[v + 1];
    float acc = 0.f;
    for (; i < end; i++) {
        int u = d_sorted_end[i];
        float w = d_sorted_val[i];
        acc = fmaf(w, d_out0[(size_t)u * 256 + t], acc);
    }
    d_z1[(size_t)v * 256 + t] = acc * d_deginv[v];
}

// ---------------- tensor-core concat-GEMM via mma.sync (bf16 hi/lo compensated) ----------------
// CTA: 128 rows x 128 cols, 256 threads = 8 warps (4m x 2n), warp tile 32x64.
// K processed in 64-wide chunks; A chunks converted fp32->bf16 hi/lo into a
// double-buffered padded smem tile; B (weights) resident in smem whole kernel.
// smem: [0,512) bias, [1024, 1024+NC*36864) B image, then 2 A stages of 36864 B.
template <int NC, bool L0F>
__global__ void __launch_bounds__(256) k_gemm_mma(const float* __restrict__ xin,
                                                  const float* __restrict__ bias) {
    extern __shared__ unsigned char sm[];
    const int SBOFF = 1024;
    const int SAOFF = 1024 + NC * 36864;
    int tid = threadIdx.x;
    int wid = tid >> 5;
    int lane = tid & 31;
    int tile = blockIdx.x;
    int wm = (wid & 3) * 32;
    int wn = (wid >> 2) * 64;

    // copy B image + bias
    {
        const uint4* bsrc = L0F ? d_Bimg0 : d_Bimg1;
        uint4* bdst = (uint4*)(sm + SBOFF);
        for (int i = tid; i < NC * 2304; i += 256) bdst[i] = bsrc[i];
        if (tid < 128) ((float*)sm)[tid] = bias[tid];
    }

    // A chunk loader: 128 rows x 64 k fp32 -> bf16 hi/lo padded tile
    int arow = tid >> 1;
    int kq = (tid & 1) * 32;
    int row = tile * 128 + arow;
    bool ok = row < NROWS;
    auto loadA = [&](int c, int stage) {
        const float* src;
        if (L0F) src = (c == 0) ? (xin + ((size_t)(row & 1) * NV + (row >> 1)) * 64)
                                : (d_z0 + (size_t)row * 64);
        else     src = (c < 2) ? (d_out0 + (size_t)row * 128 + c * 64)
                               : (d_z1 + (size_t)row * 128 + (c - 2) * 64);
        unsigned short* ahi = (unsigned short*)(sm + SAOFF + stage * 36864);
        unsigned short* alo = ahi + 128 * BST;
#pragma unroll
        for (int j = 0; j < 8; j++) {
            int kk = kq + j * 4;
            float4 v = ok ? *(const float4*)(src + kk) : make_float4(0.f, 0.f, 0.f, 0.f);
            uint32_t h0 = (uint32_t)bfb(v.x) | ((uint32_t)bfb(v.y) << 16);
            uint32_t h1 = (uint32_t)bfb(v.z) | ((uint32_t)bfb(v.w) << 16);
            uint32_t l0 = (uint32_t)bfb(v.x - bfhi(v.x)) | ((uint32_t)bfb(v.y - bfhi(v.y)) << 16);
            uint32_t l1 = (uint32_t)bfb(v.z - bfhi(v.z)) | ((uint32_t)bfb(v.w - bfhi(v.w)) << 16);
            *(uint2*)(ahi + arow * BST + kk) = make_uint2(h0, h1);
            *(uint2*)(alo + arow * BST + kk) = make_uint2(l0, l1);
        }
    };

    float acc[2][8][4];
#pragma unroll
    for (int m = 0; m < 2; m++)
#pragma unroll
        for (int nf = 0; nf < 8; nf++)
#pragma unroll
            for (int q = 0; q < 4; q++) acc[m][nf][q] = 0.f;

    uint32_t smb = smem_u32(sm);
    // precomputed ldmatrix lane-address components (elements)
    int a_r = wm + (lane & 15);
    int a_k = (lane >> 4) << 3;
    int b_n = wn + (lane & 7) + ((lane >> 4) << 3);
    int b_k = ((lane >> 3) & 1) << 3;

    auto compute = [&](int c, int stage) {
        uint32_t ahiB = smb + SAOFF + stage * 36864;
        uint32_t bhiB = smb + SBOFF + c * 36864;
#pragma unroll
        for (int ks = 0; ks < 4; ks++) {
            int k0 = ks * 16;
            uint32_t ahi[2][4], alo[2][4];
#pragma unroll
            for (int m = 0; m < 2; m++) {
                uint32_t ad = ahiB + (uint32_t)(((a_r + m * 16) * BST + k0 + a_k) * 2);
                ldmat4(ahi[m], ad);
                ldmat4(alo[m], ad + 128 * BST * 2);
            }
            uint32_t bhi[8][2], blo[8][2];
#pragma unroll
            for (int g = 0; g < 4; g++) {
                uint32_t bd = bhiB + (uint32_t)((((b_n + g * 16) * BST) + k0 + b_k) * 2);
                uint32_t t[4];
                ldmat4(t, bd);
                bhi[2 * g][0] = t[0]; bhi[2 * g][1] = t[1];
                bhi[2 * g + 1][0] = t[2]; bhi[2 * g + 1][1] = t[3];
                ldmat4(t, bd + 128 * BST * 2);
                blo[2 * g][0] = t[0]; blo[2 * g][1] = t[1];
                blo[2 * g + 1][0] = t[2]; blo[2 * g + 1][1] = t[3];
            }
#pragma unroll
            for (int m = 0; m < 2; m++)
#pragma unroll
                for (int nf = 0; nf < 8; nf++) {
                    mma_bf16(acc[m][nf], ahi[m], bhi[nf]);
                    mma_bf16(acc[m][nf], alo[m], bhi[nf]);
                    mma_bf16(acc[m][nf], ahi[m], blo[nf]);
                }
        }
    };

    loadA(0, 0);
    __syncthreads();
#pragma unroll
    for (int c = 0; c < NC; c++) {
        if (c + 1 < NC) loadA(c + 1, (c + 1) & 1);
        compute(c, c & 1);
        __syncthreads();
    }

    // epilogue: bias + (L0) leaky relu, write fp32
    float* outp = L0F ? d_out0 : d_out1;
    const float* sbias = (const float*)sm;
#pragma unroll
    for (int m = 0; m < 2; m++) {
        int r0 = tile * 128 + wm + m * 16 + (lane >> 2);
#pragma unroll
        for (int nf = 0; nf < 8; nf++) {
            int col = wn + nf * 8 + (lane & 3) * 2;
            float bx = sbias[col], by = sbias[col + 1];
            float o0 = acc[m][nf][0] + bx, o1 = acc[m][nf][1] + by;
            float o2 = acc[m][nf][2] + bx, o3 = acc[m][nf][3] + by;
            if (L0F) {
                o0 = (o0 >= 0.f) ? o0 : 0.2f * o0;
                o1 = (o1 >= 0.f) ? o1 : 0.2f * o1;
                o2 = (o2 >= 0.f) ? o2 : 0.2f * o2;
                o3 = (o3 >= 0.f) ? o3 : 0.2f * o3;
            }
            if (r0 < NROWS)     *(float2*)(outp + (size_t)r0 * 128 + col)       = make_float2(o0, o1);
            if (r0 + 8 < NROWS) *(float2*)(outp + (size_t)(r0 + 8) * 128 + col) = make_float2(o2, o3);
        }
    }
}

// ---------------- final: pool(out1) + (pool(x) @ W_res + sw * b_res) ----------------
__global__ void __launch_bounds__(256) k_final(const float* __restrict__ x,
                                               const int* __restrict__ asgnIdx,
                                               const float* __restrict__ asgnVal,
                                               const float* __restrict__ Wres,
                                               const float* __restrict__ bres,
                                               float* __restrict__ out) {
    __shared__ float xps[4][64];
    int sub = threadIdx.x >> 6;
    int p = threadIdx.x & 63;
    int r = blockIdx.x * 4 + sub;
    bool ok = r < 2 * CN;
    int c = r >> 1, b = r & 1;
    const int* fine = asgnIdx + NV;
    float sw = 0.f;
    float2 p1 = make_float2(0.f, 0.f);
    if (ok) {
        int i0 = 4 * c;
        float a = 0.f;
#pragma unroll
        for (int j = 0; j < 4; j++) {
            int f = fine[i0 + j];
            float w = asgnVal[i0 + j];
            a = fmaf(w, x[((size_t)b * NV + f) * 64 + p], a);
            sw += w;
            float2 o1 = *(const float2*)(&d_out1[(size_t)f * 256 + b * 128 + 2 * p]);
            p1.x = fmaf(w, o1.x, p1.x);
            p1.y = fmaf(w, o1.y, p1.y);
        }
        xps[sub][p] = a;
    }
    __syncthreads();
    if (ok) {
        float2 br = *(const float2*)(bres + 2 * p);
        float accx = p1.x + sw * br.x;
        float accy = p1.y + sw * br.y;
#pragma unroll 8
        for (int k = 0; k < 64; k++) {
            float xk = xps[sub][k];
            float2 w2 = *(const float2*)(Wres + k * 128 + 2 * p);
            accx = fmaf(xk, w2.x, accx);
            accy = fmaf(xk, w2.y, accy);
        }
        *(float2*)(out + ((size_t)b * CN + c) * 128 + 2 * p) = make_float2(accx, accy);
    }
}

// ---------------- launch ----------------
extern "C" void kernel_launch(void* const* d_in, const int* in_sizes, int n_in,
                              void* d_out, int out_size) {
    const float* x       = (const float*)d_in[0];
    const float* adjVal  = (const float*)d_in[1];
    const float* edgeOne = (const float*)d_in[2];
    const int*   E_start = (const int*)d_in[3];
    const int*   E_end   = (const int*)d_in[4];
    const int*   asgnIdx = (const int*)d_in[5];
    const float* asgnVal = (const float*)d_in[6];
    const float* W_res   = (const float*)d_in[7];
    const float* b_res   = (const float*)d_in[8];
    const float* W0s     = (const float*)d_in[9];
    const float* W0n     = (const float*)d_in[10];
    const float* b0      = (const float*)d_in[11];
    const float* W1s     = (const float*)d_in[12];
    const float* W1n     = (const float*)d_in[13];
    const float* b1      = (const float*)d_in[14];
    float* out = (float*)d_out;

    const int NB = (NV + 511) / 512;   // 98
    const int smA = 1024 + 2 * 36864 + 2 * 36864;   // 148480
    const int smB = 1024 + 4 * 36864 + 2 * 36864;   // 222208
    cudaFuncSetAttribute(k_gemm_mma<2, true>,  cudaFuncAttributeMaxDynamicSharedMemorySize, smA);
    cudaFuncSetAttribute(k_gemm_mma<4, false>, cudaFuncAttributeMaxDynamicSharedMemorySize, smB);

    k_prep<<<64, 256>>>(W0s, W0n, W1s, W1n);                   // 0
    k_hist<<<(NE + 255) / 256, 256>>>(E_start, edgeOne);       // 1
    k_scanA<<<NB, 512>>>();                                    // 2
    k_scanC2<<<NB, 512>>>(NB);                                 // 3
    k_fill<<<(NE + 255) / 256, 256>>>(E_start, E_end, adjVal); // 4
    k_gather64<<<NV / 2, 256>>>(x);                            // 5 <- ncu capture slot
    k_gemm_mma<2, true><<<NTILES, 256, smA>>>(x, b0);          // 6
    k_gather128<<<NV, 256>>>();                                // 7
    k_gemm_mma<4, false><<<NTILES, 256, smB>>>(x, b1);         // 8
    k_final<<<(2 * CN + 3) / 4, 256>>>(x, asgnIdx, asgnVal, W_res, b_res, out); // 9
}